// round 6
// baseline (speedup 1.0000x reference)
#include <cuda_runtime.h>
#include <math.h>

#define BB 16
#define PP 500
#define NN 501
#define EE 128
#define HH 8
#define HD 16
#define LL 3
#define LEAKY 0.2f
#define LN_EPS 1e-5f
#define IT 16
#define JT 16
#define MW 16   // mask words per row (501 bits -> 16 u32)

// Scratch (device globals; no runtime allocation)
__device__ float g_x[2][(size_t)BB * NN * EE];
__device__ float g_xW[(size_t)BB * NN * EE];
__device__ float g_ei[BB * NN * HH];
__device__ float g_ej[BB * NN * HH];
__device__ unsigned int g_adjbits[BB * NN * MW];
__device__ int g_mask_kind;

__device__ __forceinline__ void ffma2(unsigned long long& acc,
                                      unsigned long long x,
                                      unsigned long long p) {
    asm("fma.rn.f32x2 %0, %1, %2, %0;" : "+l"(acc) : "l"(x), "l"(p));
}
__device__ __forceinline__ void fadd2(unsigned long long& acc,
                                      unsigned long long p) {
    asm("add.rn.f32x2 %0, %0, %1;" : "+l"(acc) : "l"(p));
}
__device__ __forceinline__ float2 u2f2(unsigned long long u) {
    float2 r;
    r.x = __uint_as_float((unsigned)u);
    r.y = __uint_as_float((unsigned)(u >> 32));
    return r;
}
__device__ __forceinline__ unsigned long long rep2(float v) {
    unsigned int u = __float_as_uint(v);
    return ((unsigned long long)u << 32) | u;
}

// ---------------------------------------------------------------------------
__global__ void probe_mask_kernel(const unsigned int* __restrict__ w) {
    __shared__ int s_u8, s_f32;
    if (threadIdx.x == 0) { s_u8 = 0; s_f32 = 0; }
    __syncthreads();
    for (int idx = threadIdx.x; idx < 4096; idx += blockDim.x) {
        unsigned int v = w[idx];
        if (v == 0x3f800000u) atomicOr(&s_f32, 1);
        else if (v > 1u)      atomicOr(&s_u8, 1);
    }
    __syncthreads();
    if (threadIdx.x == 0) g_mask_kind = s_f32 ? 2 : (s_u8 ? 1 : 0);
}

// grid = B*N blocks, 512 threads. Warp w emits mask word w via ballot.
__global__ void convert_bits_kernel(const void* __restrict__ adj_raw) {
    int bn = blockIdx.x;
    int t = threadIdx.x;
    int kind = g_mask_kind;
    bool v = false;
    if (t < NN) {
        size_t idx = (size_t)bn * NN + t;
        if (kind == 1)      v = ((const unsigned char*)adj_raw)[idx] != 0;
        else if (kind == 2) v = ((const float*)adj_raw)[idx] != 0.0f;
        else                v = ((const int*)adj_raw)[idx] != 0;
    }
    unsigned int word = __ballot_sync(0xffffffffu, v);
    if ((t & 31) == 0) g_adjbits[bn * MW + (t >> 5)] = word;
}

// ---------------------------------------------------------------------------
__global__ void embed_kernel(const float* __restrict__ depot_xy,
                             const float* __restrict__ node5,
                             const float* __restrict__ depW,
                             const float* __restrict__ depb,
                             const float* __restrict__ nodeW,
                             const float* __restrict__ nodeb) {
    int bn = blockIdx.x;
    int b = bn / NN, n = bn % NN;
    int e = threadIdx.x;
    float v;
    if (n == 0) {
        float x0 = depot_xy[b * 2 + 0];
        float x1 = depot_xy[b * 2 + 1];
        v = fmaf(x0, depW[0 * EE + e], fmaf(x1, depW[1 * EE + e], depb[e]));
    } else {
        int p = n - 1;
        const float* f = node5 + ((size_t)b * PP + p) * 5;
        v = nodeb[e];
        #pragma unroll
        for (int k = 0; k < 5; k++) v = fmaf(f[k], nodeW[k * EE + e], v);
    }
    g_x[0][(size_t)bn * EE + e] = v;
}

// ---------------------------------------------------------------------------
// xW = x @ W[l] + fused ei/ej. grid = 501, block = 256, 16 rows/block.
// ---------------------------------------------------------------------------
__global__ void __launch_bounds__(256) xw_kernel(int src,
                                                const float* __restrict__ Wl,
                                                const float* __restrict__ attn_l) {
    int t = threadIdx.x;
    int e = t & 127, half = t >> 7;
    int row0 = blockIdx.x * 16;
    __shared__ float xs[16][EE];
    const float* x = &g_x[src][0];
    {
        const float4* s4 = (const float4*)(x + (size_t)row0 * EE);
        float4* d4 = (float4*)&xs[0][0];
        for (int idx = t; idx < 16 * EE / 4; idx += 256) d4[idx] = s4[idx];
    }
    __syncthreads();

    float acc[8];
    #pragma unroll
    for (int r = 0; r < 8; r++) acc[r] = 0.f;

    for (int k = 0; k < EE; k += 4) {
        float w0 = Wl[(k + 0) * EE + e];
        float w1 = Wl[(k + 1) * EE + e];
        float w2 = Wl[(k + 2) * EE + e];
        float w3 = Wl[(k + 3) * EE + e];
        #pragma unroll
        for (int r = 0; r < 8; r++) {
            float4 xv = *(const float4*)&xs[half * 8 + r][k];
            acc[r] = fmaf(xv.x, w0, acc[r]);
            acc[r] = fmaf(xv.y, w1, acc[r]);
            acc[r] = fmaf(xv.z, w2, acc[r]);
            acc[r] = fmaf(xv.w, w3, acc[r]);
        }
    }

    int h = e >> 4, d = e & 15;
    float a1 = attn_l[h * 2 * HD + d];
    float a2 = attn_l[h * 2 * HD + HD + d];
    #pragma unroll
    for (int r = 0; r < 8; r++) {
        int row = row0 + half * 8 + r;
        g_xW[(size_t)row * EE + e] = acc[r];
        float vi = acc[r] * a1, vj = acc[r] * a2;
        #pragma unroll
        for (int off = 8; off; off >>= 1) {
            vi += __shfl_down_sync(0xffffffffu, vi, off, 16);
            vj += __shfl_down_sync(0xffffffffu, vj, off, 16);
        }
        if (d == 0) { g_ei[row * HH + h] = vi; g_ej[row * HH + h] = vj; }
    }
}

// ---------------------------------------------------------------------------
// Attention + residual + LayerNorm + ELU.
// grid = (32, B), block = 128 (4 warps). Warp w: rows i0+4w..i0+4w+3 (two
// row-PAIRS packed in f32x2), all 128 cols (lane c: cols 4c..4c+3).
// Softmax shift m = leaky(ei + max_all_j ej)  (upper bound; shift cancels).
// ---------------------------------------------------------------------------
__global__ void __launch_bounds__(128) attn_kernel(const float* __restrict__ gamma,
                                                   const float* __restrict__ beta,
                                                   int dst, float* __restrict__ dout) {
    int b = blockIdx.y;
    int i0 = blockIdx.x * IT;
    int t = threadIdx.x;

    __shared__ float ej_s[NN * HH];                      // 16032 B
    __shared__ float ei_s[IT * HH];                      // 512 B
    __shared__ float m_s[IT * HH];                       // 512 B
    __shared__ float gpart[16][HH];                      // 512 B
    __shared__ float gmax[HH];
    __shared__ unsigned int mask_s[IT][MW];              // 1024 B
    __shared__ unsigned long long xs2[JT][EE];           // 16384 B (replicated)
    __shared__ unsigned int p_s[JT][(IT / 2) * HH * 2];  // 8192 B (row pairs)
    __shared__ unsigned long long s2_s[(IT / 2) * HH];   // 512 B

    const float* xWb = g_xW + (size_t)b * NN * EE;

    // stage ej (4008 floats = 1002 float4)
    {
        const float4* src = (const float4*)(g_ej + (size_t)b * NN * HH);
        float4* d4 = (float4*)ej_s;
        for (int idx = t; idx < NN * HH / 4; idx += 128) d4[idx] = src[idx];
    }
    // ei (128 floats)
    {
        int i = i0 + (t >> 3);
        ei_s[t] = (i < NN) ? g_ei[(b * NN + i) * HH + (t & 7)] : 0.f;
    }
    // mask bits: 256 words, 2 per thread
    {
        #pragma unroll
        for (int k = 0; k < 2; k++) {
            int idx = t + 128 * k;
            int ii = idx >> 4, w = idx & 15;
            int i = i0 + ii;
            mask_s[ii][w] = (i < NN) ? g_adjbits[(b * NN + i) * MW + w] : 0u;
        }
    }
    __syncthreads();

    // global per-head max of ej (valid softmax shift upper bound)
    {
        int g = t >> 3, hh = t & 7;
        float mx = -INFINITY;
        for (int j = g; j < NN; j += 16) mx = fmaxf(mx, ej_s[j * HH + hh]);
        gpart[g][hh] = mx;
    }
    __syncthreads();
    if (t < HH) {
        float mx = gpart[0][t];
        #pragma unroll
        for (int g = 1; g < 16; g++) mx = fmaxf(mx, gpart[g][t]);
        gmax[t] = mx;
    }
    __syncthreads();
    {
        float w = ei_s[t] + gmax[t & 7];
        m_s[t] = fmaxf(w, LEAKY * w);
    }
    __syncthreads();

    int c = t & 31;           // lane: cols 4c..4c+3
    int warp = t >> 5;        // rows 4*warp .. 4*warp+3
    int h = c >> 2;
    bool sowner = ((c & 3) == 0);

    unsigned long long acc64[2][4];
    unsigned long long sacc2[2] = {0ull, 0ull};
    #pragma unroll
    for (int r = 0; r < 2; r++)
        #pragma unroll
        for (int q = 0; q < 4; q++) acc64[r][q] = 0ull;

    for (int j0 = 0; j0 < NN; j0 += JT) {
        // stage xW j-tile, pre-replicated as (v,v) u64
        #pragma unroll
        for (int k = 0; k < 4; k++) {
            int f4 = t + 128 * k;               // 0..511
            int jj = f4 >> 5, c4 = f4 & 31;
            int j = j0 + jj;
            float4 xv = (j < NN) ? ((const float4*)(xWb + (size_t)j * EE))[c4]
                                 : make_float4(0.f, 0.f, 0.f, 0.f);
            ulonglong2* dst2 = (ulonglong2*)&xs2[jj][c4 * 4];
            dst2[0] = make_ulonglong2(rep2(xv.x), rep2(xv.y));
            dst2[1] = make_ulonglong2(rep2(xv.z), rep2(xv.w));
        }
        // p for this tile: item (ii, jj), all 8 heads
        #pragma unroll
        for (int k = 0; k < 2; k++) {
            int item = t + 128 * k;             // 0..255
            int ii = item >> 4, jj = item & 15;
            int j = j0 + jj;
            unsigned int* pd = &p_s[jj][((ii >> 1) * HH) * 2 + (ii & 1)];
            if ((mask_s[ii][j >> 5] >> (j & 31)) & 1u) {
                #pragma unroll
                for (int hh = 0; hh < HH; hh++) {
                    float w = ei_s[ii * HH + hh] + ej_s[j * HH + hh];
                    w = fmaxf(w, LEAKY * w);
                    pd[hh * 2] = __float_as_uint(__expf(w - m_s[ii * HH + hh]));
                }
            } else {
                #pragma unroll
                for (int hh = 0; hh < HH; hh++) pd[hh * 2] = 0u;
            }
        }
        __syncthreads();

        #pragma unroll 4
        for (int jj = 0; jj < JT; jj++) {
            ulonglong2 xa = *(const ulonglong2*)&xs2[jj][4 * c];
            ulonglong2 xb = *(const ulonglong2*)&xs2[jj][4 * c + 2];
            #pragma unroll
            for (int r = 0; r < 2; r++) {
                unsigned long long pv =
                    *(const unsigned long long*)&p_s[jj][((warp * 2 + r) * HH + h) * 2];
                ffma2(acc64[r][0], xa.x, pv);
                ffma2(acc64[r][1], xa.y, pv);
                ffma2(acc64[r][2], xb.x, pv);
                ffma2(acc64[r][3], xb.y, pv);
                if (sowner) fadd2(sacc2[r], pv);
            }
        }
        __syncthreads();
    }

    if (sowner) {
        #pragma unroll
        for (int r = 0; r < 2; r++) s2_s[(warp * 2 + r) * HH + h] = sacc2[r];
    }
    __syncthreads();

    // Epilogue
    float* o = (dst < 0) ? dout : &g_x[dst][0];
    float4 gv = *(const float4*)&gamma[4 * c];
    float4 bv = *(const float4*)&beta[4 * c];

    #pragma unroll
    for (int r = 0; r < 2; r++) {
        float2 sv = u2f2(s2_s[(warp * 2 + r) * HH + h]);
        int ilo = i0 + warp * 4 + 2 * r;
        int ihi = ilo + 1;
        float2 a0 = u2f2(acc64[r][0]);
        float2 a1 = u2f2(acc64[r][1]);
        float2 a2 = u2f2(acc64[r][2]);
        float2 a3 = u2f2(acc64[r][3]);

        // row lo
        if (ilo < NN) {
            float inv = 1.f / sv.x;
            float4 xwv = *(const float4*)(xWb + (size_t)ilo * EE + 4 * c);
            float v0 = a0.x * inv + xwv.x;
            float v1 = a1.x * inv + xwv.y;
            float v2 = a2.x * inv + xwv.z;
            float v3 = a3.x * inv + xwv.w;
            float s1 = v0 + v1 + v2 + v3;
            float s2 = v0 * v0 + v1 * v1 + v2 * v2 + v3 * v3;
            #pragma unroll
            for (int off = 16; off; off >>= 1) {
                s1 += __shfl_xor_sync(0xffffffffu, s1, off);
                s2 += __shfl_xor_sync(0xffffffffu, s2, off);
            }
            float mu = s1 * (1.f / EE);
            float var = s2 * (1.f / EE) - mu * mu;
            float rstd = rsqrtf(var + LN_EPS);
            float y0 = (v0 - mu) * rstd * gv.x + bv.x;
            float y1 = (v1 - mu) * rstd * gv.y + bv.y;
            float y2 = (v2 - mu) * rstd * gv.z + bv.z;
            float y3 = (v3 - mu) * rstd * gv.w + bv.w;
            y0 = y0 > 0.f ? y0 : expm1f(y0);
            y1 = y1 > 0.f ? y1 : expm1f(y1);
            y2 = y2 > 0.f ? y2 : expm1f(y2);
            y3 = y3 > 0.f ? y3 : expm1f(y3);
            *(float4*)(o + ((size_t)(b * NN + ilo)) * EE + 4 * c) =
                make_float4(y0, y1, y2, y3);
        }
        // row hi
        if (ihi < NN) {
            float inv = 1.f / sv.y;
            float4 xwv = *(const float4*)(xWb + (size_t)ihi * EE + 4 * c);
            float v0 = a0.y * inv + xwv.x;
            float v1 = a1.y * inv + xwv.y;
            float v2 = a2.y * inv + xwv.z;
            float v3 = a3.y * inv + xwv.w;
            float s1 = v0 + v1 + v2 + v3;
            float s2 = v0 * v0 + v1 * v1 + v2 * v2 + v3 * v3;
            #pragma unroll
            for (int off = 16; off; off >>= 1) {
                s1 += __shfl_xor_sync(0xffffffffu, s1, off);
                s2 += __shfl_xor_sync(0xffffffffu, s2, off);
            }
            float mu = s1 * (1.f / EE);
            float var = s2 * (1.f / EE) - mu * mu;
            float rstd = rsqrtf(var + LN_EPS);
            float y0 = (v0 - mu) * rstd * gv.x + bv.x;
            float y1 = (v1 - mu) * rstd * gv.y + bv.y;
            float y2 = (v2 - mu) * rstd * gv.z + bv.z;
            float y3 = (v3 - mu) * rstd * gv.w + bv.w;
            y0 = y0 > 0.f ? y0 : expm1f(y0);
            y1 = y1 > 0.f ? y1 : expm1f(y1);
            y2 = y2 > 0.f ? y2 : expm1f(y2);
            y3 = y3 > 0.f ? y3 : expm1f(y3);
            *(float4*)(o + ((size_t)(b * NN + ihi)) * EE + 4 * c) =
                make_float4(y0, y1, y2, y3);
        }
    }
}

// ---------------------------------------------------------------------------
extern "C" void kernel_launch(void* const* d_in, const int* in_sizes, int n_in,
                              void* d_out, int out_size) {
    const float* depot_xy = (const float*)d_in[0];
    const float* node5    = (const float*)d_in[1];
    const void*  adj_raw  = (const void*)d_in[2];
    const float* depW  = (const float*)d_in[3];
    const float* depb  = (const float*)d_in[4];
    const float* nodeW = (const float*)d_in[5];
    const float* nodeb = (const float*)d_in[6];
    const float* W     = (const float*)d_in[7];
    const float* attn  = (const float*)d_in[8];
    const float* ln_g  = (const float*)d_in[9];
    const float* ln_b  = (const float*)d_in[10];
    float* out = (float*)d_out;

    probe_mask_kernel<<<1, 256>>>((const unsigned int*)adj_raw);
    convert_bits_kernel<<<BB * NN, 512>>>(adj_raw);

    embed_kernel<<<BB * NN, EE>>>(depot_xy, node5, depW, depb, nodeW, nodeb);

    dim3 agrid((NN + IT - 1) / IT, BB);
    int cur = 0;
    for (int l = 0; l < LL; l++) {
        xw_kernel<<<BB * NN / 16, 256>>>(cur,
                                         W + (size_t)l * EE * EE,
                                         attn + (size_t)l * HH * 2 * HD);
        int dst = (l == LL - 1) ? -1 : (1 - cur);
        attn_kernel<<<agrid, 128>>>(ln_g + (size_t)l * EE,
                                    ln_b + (size_t)l * EE,
                                    dst, out);
        cur = 1 - cur;
    }
}

// round 7
// speedup vs baseline: 1.6638x; 1.6638x over previous
#include <cuda_runtime.h>
#include <math.h>

#define BB 16
#define PP 500
#define NN 501
#define EE 128
#define HH 8
#define HD 16
#define LL 3
#define LEAKY 0.2f
#define LN_EPS 1e-5f
#define IT 16
#define JT 16
#define MW 16   // mask words per row (501 bits -> 16 u32)

// Scratch (device globals; no runtime allocation)
__device__ float g_x[2][(size_t)BB * NN * EE];
__device__ float g_xW[(size_t)BB * NN * EE];
__device__ float g_ei[BB * NN * HH];
__device__ float g_ej[BB * NN * HH];
__device__ unsigned int g_adjbits[BB * NN * MW];
__device__ int g_mask_kind;

// FFMA-only exp, rel err ~2e-7, no MUFU.
__device__ __forceinline__ float fast_exp(float x) {
    x = fmaxf(x, -80.f);
    float y = x * 1.4426950408889634f;
    float t = y + 12582912.f;                 // RN round to int in mantissa
    int n = __float_as_int(t) - 0x4B400000;
    float f = y - (t - 12582912.f);           // f in [-0.5, 0.5]
    float u = f * 0.6931471805599453f;
    float r = fmaf(u, 1.38888889e-3f, 8.33333333e-3f);  // 1/720, 1/120
    r = fmaf(r, u, 4.16666667e-2f);           // 1/24
    r = fmaf(r, u, 1.66666667e-1f);           // 1/6
    r = fmaf(r, u, 0.5f);
    r = fmaf(r, u, 1.0f);
    r = fmaf(r, u, 1.0f);
    return r * __int_as_float((n + 127) << 23);
}

// ---------------------------------------------------------------------------
__global__ void probe_mask_kernel(const unsigned int* __restrict__ w) {
    __shared__ int s_u8, s_f32;
    if (threadIdx.x == 0) { s_u8 = 0; s_f32 = 0; }
    __syncthreads();
    for (int idx = threadIdx.x; idx < 4096; idx += blockDim.x) {
        unsigned int v = w[idx];
        if (v == 0x3f800000u) atomicOr(&s_f32, 1);
        else if (v > 1u)      atomicOr(&s_u8, 1);
    }
    __syncthreads();
    if (threadIdx.x == 0) g_mask_kind = s_f32 ? 2 : (s_u8 ? 1 : 0);
}

// grid = B*N blocks, 512 threads. Warp w emits mask word w via ballot.
__global__ void convert_bits_kernel(const void* __restrict__ adj_raw) {
    int bn = blockIdx.x;
    int t = threadIdx.x;
    int kind = g_mask_kind;
    bool v = false;
    if (t < NN) {
        size_t idx = (size_t)bn * NN + t;
        if (kind == 1)      v = ((const unsigned char*)adj_raw)[idx] != 0;
        else if (kind == 2) v = ((const float*)adj_raw)[idx] != 0.0f;
        else                v = ((const int*)adj_raw)[idx] != 0;
    }
    unsigned int word = __ballot_sync(0xffffffffu, v);
    if ((t & 31) == 0) g_adjbits[bn * MW + (t >> 5)] = word;
}

// ---------------------------------------------------------------------------
__global__ void embed_kernel(const float* __restrict__ depot_xy,
                             const float* __restrict__ node5,
                             const float* __restrict__ depW,
                             const float* __restrict__ depb,
                             const float* __restrict__ nodeW,
                             const float* __restrict__ nodeb) {
    int bn = blockIdx.x;
    int b = bn / NN, n = bn % NN;
    int e = threadIdx.x;
    float v;
    if (n == 0) {
        float x0 = depot_xy[b * 2 + 0];
        float x1 = depot_xy[b * 2 + 1];
        v = fmaf(x0, depW[0 * EE + e], fmaf(x1, depW[1 * EE + e], depb[e]));
    } else {
        int p = n - 1;
        const float* f = node5 + ((size_t)b * PP + p) * 5;
        v = nodeb[e];
        #pragma unroll
        for (int k = 0; k < 5; k++) v = fmaf(f[k], nodeW[k * EE + e], v);
    }
    g_x[0][(size_t)bn * EE + e] = v;
}

// ---------------------------------------------------------------------------
// xW = x @ W[l] + fused ei/ej. grid = 501, block = 256, 16 rows/block.
// ---------------------------------------------------------------------------
__global__ void __launch_bounds__(256) xw_kernel(int src,
                                                const float* __restrict__ Wl,
                                                const float* __restrict__ attn_l) {
    int t = threadIdx.x;
    int e = t & 127, half = t >> 7;
    int row0 = blockIdx.x * 16;
    __shared__ float xs[16][EE];
    const float* x = &g_x[src][0];
    {
        const float4* s4 = (const float4*)(x + (size_t)row0 * EE);
        float4* d4 = (float4*)&xs[0][0];
        for (int idx = t; idx < 16 * EE / 4; idx += 256) d4[idx] = s4[idx];
    }
    __syncthreads();

    float acc[8];
    #pragma unroll
    for (int r = 0; r < 8; r++) acc[r] = 0.f;

    for (int k = 0; k < EE; k += 4) {
        float w0 = Wl[(k + 0) * EE + e];
        float w1 = Wl[(k + 1) * EE + e];
        float w2 = Wl[(k + 2) * EE + e];
        float w3 = Wl[(k + 3) * EE + e];
        #pragma unroll
        for (int r = 0; r < 8; r++) {
            float4 xv = *(const float4*)&xs[half * 8 + r][k];
            acc[r] = fmaf(xv.x, w0, acc[r]);
            acc[r] = fmaf(xv.y, w1, acc[r]);
            acc[r] = fmaf(xv.z, w2, acc[r]);
            acc[r] = fmaf(xv.w, w3, acc[r]);
        }
    }

    int h = e >> 4, d = e & 15;
    float a1 = attn_l[h * 2 * HD + d];
    float a2 = attn_l[h * 2 * HD + HD + d];
    #pragma unroll
    for (int r = 0; r < 8; r++) {
        int row = row0 + half * 8 + r;
        g_xW[(size_t)row * EE + e] = acc[r];
        float vi = acc[r] * a1, vj = acc[r] * a2;
        #pragma unroll
        for (int off = 8; off; off >>= 1) {
            vi += __shfl_down_sync(0xffffffffu, vi, off, 16);
            vj += __shfl_down_sync(0xffffffffu, vj, off, 16);
        }
        if (d == 0) { g_ei[row * HH + h] = vi; g_ej[row * HH + h] = vj; }
    }
}

// ---------------------------------------------------------------------------
// Attention + residual + LayerNorm + ELU. grid = (32, B), block = 256.
// Factorized softmax: m = leaky(ei + max_all_j ej);
//   w>=0: p = Pi*Qj  (Pi=exp(ei-m), Qj=exp(ej))
//   w<0:  p = Ri*Sj  (Ri=exp(0.2ei-m), Sj=exp(0.2ej))
//   branch: Pi*Qj >= Ti (= exp(-m))  <=>  ei+ej >= 0.
// All exps via fast_exp (FMA pipe only; zero MUFU in bulk path).
// ---------------------------------------------------------------------------
__global__ void __launch_bounds__(256) attn_kernel(const float* __restrict__ gamma,
                                                   const float* __restrict__ beta,
                                                   int dst, float* __restrict__ dout) {
    int b = blockIdx.y;
    int i0 = blockIdx.x * IT;
    int t = threadIdx.x;

    __shared__ float Pi_s[IT * HH], Ri_s[IT * HH], Ti_s[IT * HH];  // 3*512 B
    __shared__ float gpart[32][HH];                                 // 1024 B
    __shared__ float gmax[HH];
    __shared__ unsigned int mask_s[IT][MW];                         // 1024 B
    __shared__ float xs[JT][EE];                                    // 8192 B
    __shared__ float p_s[JT][IT * HH];                              // 8192 B
    __shared__ float Qt[JT][HH], St[JT][HH];                        // 2*512 B
    __shared__ float s_s[IT * HH];                                  // 512 B
    __shared__ float lnred[8][4][2];

    const float* xWb = g_xW + (size_t)b * NN * EE;
    const float* ejb = g_ej + (size_t)b * NN * HH;

    // global per-head max of ej
    {
        int g = t >> 3, hh = t & 7;
        float mx = -INFINITY;
        for (int j = g; j < NN; j += 32) mx = fmaxf(mx, ejb[j * HH + hh]);
        gpart[g][hh] = mx;
    }
    // mask bits
    {
        int ii = t >> 4, w = t & 15;
        int i = i0 + ii;
        mask_s[ii][w] = (i < NN) ? g_adjbits[(b * NN + i) * MW + w] : 0u;
    }
    __syncthreads();
    if (t < HH) {
        float mx = gpart[0][t];
        #pragma unroll
        for (int g = 1; g < 32; g++) mx = fmaxf(mx, gpart[g][t]);
        gmax[t] = mx;
    }
    __syncthreads();
    // per-i factors
    if (t < IT * HH) {
        int i = i0 + (t >> 3);
        float ei = (i < NN) ? g_ei[(b * NN + i) * HH + (t & 7)] : 0.f;
        float w = ei + gmax[t & 7];
        float m = fmaxf(w, LEAKY * w);
        Pi_s[t] = fast_exp(ei - m);
        Ri_s[t] = fast_exp(0.2f * ei - m);
        Ti_s[t] = fast_exp(-m);
    }
    __syncthreads();

    int c = t & 63;          // float2 column: cols 2c, 2c+1
    int grp = t >> 6;        // rows grp*4 .. grp*4+3
    int h = c >> 3;
    bool sowner = ((c & 7) == 0);
    float2 acc[4];
    float sacc[4];
    #pragma unroll
    for (int r = 0; r < 4; r++) { acc[r] = make_float2(0.f, 0.f); sacc[r] = 0.f; }

    for (int j0 = 0; j0 < NN; j0 += JT) {
        // stage xW j-tile + per-tile Qj/Sj factors
        {
            float4* d4 = (float4*)&xs[0][0];
            #pragma unroll
            for (int k = 0; k < 2; k++) {
                int idx = t + 256 * k;
                int jj = idx >> 5;
                int j = j0 + jj;
                d4[idx] = (j < NN) ? ((const float4*)(xWb + (size_t)j * EE))[idx & 31]
                                   : make_float4(0.f, 0.f, 0.f, 0.f);
            }
        }
        if (t < JT * HH) {
            int jj = t >> 3, hh = t & 7;
            int j = j0 + jj;
            float e = (j < NN) ? ejb[j * HH + hh] : 0.f;
            Qt[jj][hh] = fast_exp(e);
            St[jj][hh] = fast_exp(0.2f * e);
        }
        __syncthreads();

        // p for this tile: 2048 items, 8 per thread
        #pragma unroll
        for (int k = 0; k < 8; k++) {
            int idx = t + 256 * k;
            int jj = idx >> 7, ph = idx & 127;
            int ii = ph >> 3, hh = ph & 7;
            int j = j0 + jj;
            float p = 0.f;
            if ((mask_s[ii][j >> 5] >> (j & 31)) & 1u) {
                float prod = Pi_s[ph] * Qt[jj][hh];
                float pneg = Ri_s[ph] * St[jj][hh];
                p = (prod >= Ti_s[ph]) ? prod : pneg;
            }
            p_s[jj][ph] = p;
        }
        __syncthreads();

        #pragma unroll 4
        for (int jj = 0; jj < JT; jj++) {
            float2 xv = *(const float2*)&xs[jj][2 * c];
            #pragma unroll
            for (int r = 0; r < 4; r++) {
                float pv = p_s[jj][(grp * 4 + r) * HH + h];
                acc[r].x = fmaf(pv, xv.x, acc[r].x);
                acc[r].y = fmaf(pv, xv.y, acc[r].y);
                if (sowner) sacc[r] += pv;
            }
        }
        __syncthreads();
    }

    if (sowner) {
        #pragma unroll
        for (int r = 0; r < 4; r++) s_s[(grp * 4 + r) * HH + h] = sacc[r];
    }
    __syncthreads();

    // epilogue: normalize, residual, LayerNorm, ELU
    float2 val[4];
    float s1[4], s2[4];
    #pragma unroll
    for (int r = 0; r < 4; r++) {
        int ii = grp * 4 + r;
        int i = i0 + ii;
        float sv = s_s[ii * HH + h];
        float2 xwv = (i < NN) ? *(const float2*)(xWb + (size_t)i * EE + 2 * c)
                              : make_float2(0.f, 0.f);
        float inv = 1.f / sv;
        val[r].x = acc[r].x * inv + xwv.x;
        val[r].y = acc[r].y * inv + xwv.y;
        s1[r] = val[r].x + val[r].y;
        s2[r] = val[r].x * val[r].x + val[r].y * val[r].y;
    }
    #pragma unroll
    for (int off = 16; off; off >>= 1) {
        #pragma unroll
        for (int r = 0; r < 4; r++) {
            s1[r] += __shfl_xor_sync(0xffffffffu, s1[r], off);
            s2[r] += __shfl_xor_sync(0xffffffffu, s2[r], off);
        }
    }
    int warp = t >> 5;
    if ((t & 31) == 0) {
        #pragma unroll
        for (int r = 0; r < 4; r++) { lnred[warp][r][0] = s1[r]; lnred[warp][r][1] = s2[r]; }
    }
    __syncthreads();

    float* o = (dst < 0) ? dout : &g_x[dst][0];
    int w0 = grp * 2;
    float gx = gamma[2 * c], gy = gamma[2 * c + 1];
    float bx = beta[2 * c],  by = beta[2 * c + 1];
    #pragma unroll
    for (int r = 0; r < 4; r++) {
        int ii = grp * 4 + r;
        int i = i0 + ii;
        if (i >= NN) continue;
        float a = lnred[w0][r][0] + lnred[w0 + 1][r][0];
        float q = lnred[w0][r][1] + lnred[w0 + 1][r][1];
        float mu = a * (1.f / EE);
        float var = q * (1.f / EE) - mu * mu;
        float rstd = rsqrtf(var + LN_EPS);
        float yx = (val[r].x - mu) * rstd * gx + bx;
        float yy = (val[r].y - mu) * rstd * gy + by;
        yx = yx > 0.f ? yx : (fast_exp(yx) - 1.f);
        yy = yy > 0.f ? yy : (fast_exp(yy) - 1.f);
        *(float2*)(o + ((size_t)(b * NN + i)) * EE + 2 * c) = make_float2(yx, yy);
    }
}

// ---------------------------------------------------------------------------
extern "C" void kernel_launch(void* const* d_in, const int* in_sizes, int n_in,
                              void* d_out, int out_size) {
    const float* depot_xy = (const float*)d_in[0];
    const float* node5    = (const float*)d_in[1];
    const void*  adj_raw  = (const void*)d_in[2];
    const float* depW  = (const float*)d_in[3];
    const float* depb  = (const float*)d_in[4];
    const float* nodeW = (const float*)d_in[5];
    const float* nodeb = (const float*)d_in[6];
    const float* W     = (const float*)d_in[7];
    const float* attn  = (const float*)d_in[8];
    const float* ln_g  = (const float*)d_in[9];
    const float* ln_b  = (const float*)d_in[10];
    float* out = (float*)d_out;

    probe_mask_kernel<<<1, 256>>>((const unsigned int*)adj_raw);
    convert_bits_kernel<<<BB * NN, 512>>>(adj_raw);

    embed_kernel<<<BB * NN, EE>>>(depot_xy, node5, depW, depb, nodeW, nodeb);

    dim3 agrid((NN + IT - 1) / IT, BB);
    int cur = 0;
    for (int l = 0; l < LL; l++) {
        xw_kernel<<<BB * NN / 16, 256>>>(cur,
                                         W + (size_t)l * EE * EE,
                                         attn + (size_t)l * HH * 2 * HD);
        int dst = (l == LL - 1) ? -1 : (1 - cur);
        attn_kernel<<<agrid, 256>>>(ln_g + (size_t)l * EE,
                                    ln_b + (size_t)l * EE,
                                    dst, out);
        cur = 1 - cur;
    }
}

// round 10
// speedup vs baseline: 2.0188x; 1.2134x over previous
#include <cuda_runtime.h>
#include <math.h>

#define BB 16
#define PP 500
#define NN 501
#define EE 128
#define HH 8
#define HD 16
#define LL 3
#define LEAKY 0.2f
#define LN_EPS 1e-5f
#define IT 16
#define JT 16
#define MW 16    // mask words per row (501 bits -> 16 u32)
#define PROW 132 // padded p row: 8*16 + 4

// Scratch (device globals; no runtime allocation)
__device__ float g_x[2][(size_t)BB * NN * EE];
__device__ float g_xW[(size_t)BB * NN * EE];
__device__ float g_ei[BB * NN * HH];
__device__ float g_ej[BB * NN * HH];
__device__ unsigned int g_adjbits[BB * NN * MW];
__device__ int g_mask_kind;

// FFMA-only exp, rel err ~2e-7, no MUFU.
__device__ __forceinline__ float fast_exp(float x) {
    x = fmaxf(x, -80.f);
    float y = x * 1.4426950408889634f;
    float t = y + 12582912.f;
    int n = __float_as_int(t) - 0x4B400000;
    float f = y - (t - 12582912.f);
    float u = f * 0.6931471805599453f;
    float r = fmaf(u, 1.38888889e-3f, 8.33333333e-3f);
    r = fmaf(r, u, 4.16666667e-2f);
    r = fmaf(r, u, 1.66666667e-1f);
    r = fmaf(r, u, 0.5f);
    r = fmaf(r, u, 1.0f);
    r = fmaf(r, u, 1.0f);
    return r * __int_as_float((n + 127) << 23);
}
__device__ __forceinline__ float fsel_ge(float a, float b, float thr) {
    return (a >= thr) ? a : b;
}

// ---------------------------------------------------------------------------
__global__ void probe_mask_kernel(const unsigned int* __restrict__ w) {
    __shared__ int s_u8, s_f32;
    if (threadIdx.x == 0) { s_u8 = 0; s_f32 = 0; }
    __syncthreads();
    for (int idx = threadIdx.x; idx < 4096; idx += blockDim.x) {
        unsigned int v = w[idx];
        if (v == 0x3f800000u) atomicOr(&s_f32, 1);
        else if (v > 1u)      atomicOr(&s_u8, 1);
    }
    __syncthreads();
    if (threadIdx.x == 0) g_mask_kind = s_f32 ? 2 : (s_u8 ? 1 : 0);
}

__global__ void convert_bits_kernel(const void* __restrict__ adj_raw) {
    int bn = blockIdx.x;
    int t = threadIdx.x;
    int kind = g_mask_kind;
    bool v = false;
    if (t < NN) {
        size_t idx = (size_t)bn * NN + t;
        if (kind == 1)      v = ((const unsigned char*)adj_raw)[idx] != 0;
        else if (kind == 2) v = ((const float*)adj_raw)[idx] != 0.0f;
        else                v = ((const int*)adj_raw)[idx] != 0;
    }
    unsigned int word = __ballot_sync(0xffffffffu, v);
    if ((t & 31) == 0) g_adjbits[bn * MW + (t >> 5)] = word;
}

// ---------------------------------------------------------------------------
__global__ void embed_kernel(const float* __restrict__ depot_xy,
                             const float* __restrict__ node5,
                             const float* __restrict__ depW,
                             const float* __restrict__ depb,
                             const float* __restrict__ nodeW,
                             const float* __restrict__ nodeb) {
    int bn = blockIdx.x;
    int b = bn / NN, n = bn % NN;
    int e = threadIdx.x;
    float v;
    if (n == 0) {
        float x0 = depot_xy[b * 2 + 0];
        float x1 = depot_xy[b * 2 + 1];
        v = fmaf(x0, depW[0 * EE + e], fmaf(x1, depW[1 * EE + e], depb[e]));
    } else {
        int p = n - 1;
        const float* f = node5 + ((size_t)b * PP + p) * 5;
        v = nodeb[e];
        #pragma unroll
        for (int k = 0; k < 5; k++) v = fmaf(f[k], nodeW[k * EE + e], v);
    }
    g_x[0][(size_t)bn * EE + e] = v;
}

// ---------------------------------------------------------------------------
// xW = x @ W[l] + fused ei/ej. grid = 501, block = 256, 16 rows/block.
// ---------------------------------------------------------------------------
__global__ void __launch_bounds__(256) xw_kernel(int src,
                                                const float* __restrict__ Wl,
                                                const float* __restrict__ attn_l) {
    int t = threadIdx.x;
    int e = t & 127, half = t >> 7;
    int row0 = blockIdx.x * 16;
    __shared__ float xs[16][EE];
    const float* x = &g_x[src][0];
    {
        const float4* s4 = (const float4*)(x + (size_t)row0 * EE);
        float4* d4 = (float4*)&xs[0][0];
        for (int idx = t; idx < 16 * EE / 4; idx += 256) d4[idx] = s4[idx];
    }
    __syncthreads();

    float acc[8];
    #pragma unroll
    for (int r = 0; r < 8; r++) acc[r] = 0.f;

    for (int k = 0; k < EE; k += 4) {
        float w0 = Wl[(k + 0) * EE + e];
        float w1 = Wl[(k + 1) * EE + e];
        float w2 = Wl[(k + 2) * EE + e];
        float w3 = Wl[(k + 3) * EE + e];
        #pragma unroll
        for (int r = 0; r < 8; r++) {
            float4 xv = *(const float4*)&xs[half * 8 + r][k];
            acc[r] = fmaf(xv.x, w0, acc[r]);
            acc[r] = fmaf(xv.y, w1, acc[r]);
            acc[r] = fmaf(xv.z, w2, acc[r]);
            acc[r] = fmaf(xv.w, w3, acc[r]);
        }
    }

    int h = e >> 4, d = e & 15;
    float a1 = attn_l[h * 2 * HD + d];
    float a2 = attn_l[h * 2 * HD + HD + d];
    #pragma unroll
    for (int r = 0; r < 8; r++) {
        int row = row0 + half * 8 + r;
        g_xW[(size_t)row * EE + e] = acc[r];
        float vi = acc[r] * a1, vj = acc[r] * a2;
        #pragma unroll
        for (int off = 8; off; off >>= 1) {
            vi += __shfl_down_sync(0xffffffffu, vi, off, 16);
            vj += __shfl_down_sync(0xffffffffu, vj, off, 16);
        }
        if (d == 0) { g_ei[row * HH + h] = vi; g_ej[row * HH + h] = vj; }
    }
}

// ---------------------------------------------------------------------------
// Attention + residual + LayerNorm + ELU. grid = (32, B), block = 256.
// Factorized softmax (see R7). p stored as p_s[jj][h*16+ii] (padded row 132)
// so the inner loop reads 4 rows with one LDS.128; p-compute runs one thread
// per (ii,jj) with Pi/Ri/Ti in registers.
// ---------------------------------------------------------------------------
__global__ void __launch_bounds__(256) attn_kernel(const float* __restrict__ gamma,
                                                   const float* __restrict__ beta,
                                                   int dst, float* __restrict__ dout) {
    int b = blockIdx.y;
    int i0 = blockIdx.x * IT;
    int t = threadIdx.x;

    __shared__ float Pi_s[IT * HH], Ri_s[IT * HH], Ti_s[IT * HH];
    __shared__ float gpart[32][HH];
    __shared__ float gmax[HH];
    __shared__ unsigned int mask_s[IT][MW];
    __shared__ float xs[JT][EE];          // 8192 B
    __shared__ float p_s[JT][PROW];       // 8448 B
    __shared__ float Qt[JT][HH], St[JT][HH];
    __shared__ float s_s[IT * HH];
    __shared__ float lnred[8][4][2];

    const float* xWb = g_xW + (size_t)b * NN * EE;
    const float* ejb = g_ej + (size_t)b * NN * HH;

    // global per-head max of ej
    {
        int g = t >> 3, hh = t & 7;
        float mx = -INFINITY;
        for (int j = g; j < NN; j += 32) mx = fmaxf(mx, ejb[j * HH + hh]);
        gpart[g][hh] = mx;
    }
    // mask bits
    {
        int ii = t >> 4, w = t & 15;
        int i = i0 + ii;
        mask_s[ii][w] = (i < NN) ? g_adjbits[(b * NN + i) * MW + w] : 0u;
    }
    __syncthreads();
    if (t < HH) {
        float mx = gpart[0][t];
        #pragma unroll
        for (int g = 1; g < 32; g++) mx = fmaxf(mx, gpart[g][t]);
        gmax[t] = mx;
    }
    __syncthreads();
    // per-i factors
    if (t < IT * HH) {
        int i = i0 + (t >> 3);
        float ei = (i < NN) ? g_ei[(b * NN + i) * HH + (t & 7)] : 0.f;
        float w = ei + gmax[t & 7];
        float m = fmaxf(w, LEAKY * w);
        Pi_s[t] = fast_exp(ei - m);
        Ri_s[t] = fast_exp(0.2f * ei - m);
        Ti_s[t] = fast_exp(-m);
    }
    __syncthreads();

    // thread roles
    int c = t & 63;          // float2 column: cols 2c, 2c+1
    int grp = t >> 6;        // rows grp*4 .. grp*4+3
    int h = c >> 3;
    bool sowner = ((c & 7) == 0);
    int ii_t = t >> 4;       // p-compute: row
    int jj_t = t & 15;       // p-compute: tile col

    // register-resident per-(ii) factors for p-compute
    float Pi_r[HH], Ri_r[HH], Ti_r[HH];
    #pragma unroll
    for (int hh = 0; hh < HH; hh++) {
        Pi_r[hh] = Pi_s[ii_t * HH + hh];
        Ri_r[hh] = Ri_s[ii_t * HH + hh];
        Ti_r[hh] = Ti_s[ii_t * HH + hh];
    }

    float2 acc[4];
    float sacc[4];
    #pragma unroll
    for (int r = 0; r < 4; r++) { acc[r] = make_float2(0.f, 0.f); sacc[r] = 0.f; }

    for (int j0 = 0; j0 < NN; j0 += JT) {
        // stage xW j-tile + per-tile Qj/Sj factors
        {
            float4* d4 = (float4*)&xs[0][0];
            #pragma unroll
            for (int k = 0; k < 2; k++) {
                int idx = t + 256 * k;
                int jj = idx >> 5;
                int j = j0 + jj;
                d4[idx] = (j < NN) ? ((const float4*)(xWb + (size_t)j * EE))[idx & 31]
                                   : make_float4(0.f, 0.f, 0.f, 0.f);
            }
        }
        if (t < JT * HH) {
            int jj = t >> 3, hh = t & 7;
            int j = j0 + jj;
            float e = (j < NN) ? ejb[j * HH + hh] : 0.f;
            Qt[jj][hh] = fast_exp(e);
            St[jj][hh] = fast_exp(0.2f * e);
        }
        __syncthreads();

        // p-compute: thread (ii_t, jj_t), all 8 heads
        {
            int j = j0 + jj_t;
            float* pd = &p_s[jj_t][ii_t];
            if (j < NN && ((mask_s[ii_t][j >> 5] >> (j & 31)) & 1u)) {
                float4 q0 = *(const float4*)&Qt[jj_t][0];
                float4 q1 = *(const float4*)&Qt[jj_t][4];
                float4 sp0 = *(const float4*)&St[jj_t][0];
                float4 sp1 = *(const float4*)&St[jj_t][4];
                pd[0 * 16] = fsel_ge(Pi_r[0] * q0.x, Ri_r[0] * sp0.x, Ti_r[0]);
                pd[1 * 16] = fsel_ge(Pi_r[1] * q0.y, Ri_r[1] * sp0.y, Ti_r[1]);
                pd[2 * 16] = fsel_ge(Pi_r[2] * q0.z, Ri_r[2] * sp0.z, Ti_r[2]);
                pd[3 * 16] = fsel_ge(Pi_r[3] * q0.w, Ri_r[3] * sp0.w, Ti_r[3]);
                pd[4 * 16] = fsel_ge(Pi_r[4] * q1.x, Ri_r[4] * sp1.x, Ti_r[4]);
                pd[5 * 16] = fsel_ge(Pi_r[5] * q1.y, Ri_r[5] * sp1.y, Ti_r[5]);
                pd[6 * 16] = fsel_ge(Pi_r[6] * q1.z, Ri_r[6] * sp1.z, Ti_r[6]);
                pd[7 * 16] = fsel_ge(Pi_r[7] * q1.w, Ri_r[7] * sp1.w, Ti_r[7]);
            } else {
                #pragma unroll
                for (int hh = 0; hh < HH; hh++) pd[hh * 16] = 0.f;
            }
        }
        __syncthreads();

        // inner: LDS.128 p (4 rows) + LDS.64 xv + 8 FFMA per jj
        #pragma unroll 4
        for (int jj = 0; jj < JT; jj++) {
            float4 p4 = *(const float4*)&p_s[jj][h * 16 + grp * 4];
            float2 xv = *(const float2*)&xs[jj][2 * c];
            acc[0].x = fmaf(p4.x, xv.x, acc[0].x);
            acc[0].y = fmaf(p4.x, xv.y, acc[0].y);
            acc[1].x = fmaf(p4.y, xv.x, acc[1].x);
            acc[1].y = fmaf(p4.y, xv.y, acc[1].y);
            acc[2].x = fmaf(p4.z, xv.x, acc[2].x);
            acc[2].y = fmaf(p4.z, xv.y, acc[2].y);
            acc[3].x = fmaf(p4.w, xv.x, acc[3].x);
            acc[3].y = fmaf(p4.w, xv.y, acc[3].y);
            if (sowner) {
                sacc[0] += p4.x; sacc[1] += p4.y;
                sacc[2] += p4.z; sacc[3] += p4.w;
            }
        }
        __syncthreads();
    }

    if (sowner) {
        #pragma unroll
        for (int r = 0; r < 4; r++) s_s[(grp * 4 + r) * HH + h] = sacc[r];
    }
    __syncthreads();

    // epilogue: normalize, residual, LayerNorm, ELU
    float2 val[4];
    float s1[4], s2[4];
    #pragma unroll
    for (int r = 0; r < 4; r++) {
        int ii = grp * 4 + r;
        int i = i0 + ii;
        float sv = s_s[ii * HH + h];
        float2 xwv = (i < NN) ? *(const float2*)(xWb + (size_t)i * EE + 2 * c)
                              : make_float2(0.f, 0.f);
        float inv = 1.f / sv;
        val[r].x = acc[r].x * inv + xwv.x;
        val[r].y = acc[r].y * inv + xwv.y;
        s1[r] = val[r].x + val[r].y;
        s2[r] = val[r].x * val[r].x + val[r].y * val[r].y;
    }
    #pragma unroll
    for (int off = 16; off; off >>= 1) {
        #pragma unroll
        for (int r = 0; r < 4; r++) {
            s1[r] += __shfl_xor_sync(0xffffffffu, s1[r], off);
            s2[r] += __shfl_xor_sync(0xffffffffu, s2[r], off);
        }
    }
    int warp = t >> 5;
    if ((t & 31) == 0) {
        #pragma unroll
        for (int r = 0; r < 4; r++) { lnred[warp][r][0] = s1[r]; lnred[warp][r][1] = s2[r]; }
    }
    __syncthreads();

    float* o = (dst < 0) ? dout : &g_x[dst][0];
    int w0 = grp * 2;
    float gx = gamma[2 * c], gy = gamma[2 * c + 1];
    float bx = beta[2 * c],  by = beta[2 * c + 1];
    #pragma unroll
    for (int r = 0; r < 4; r++) {
        int ii = grp * 4 + r;
        int i = i0 + ii;
        if (i >= NN) continue;
        float a = lnred[w0][r][0] + lnred[w0 + 1][r][0];
        float q = lnred[w0][r][1] + lnred[w0 + 1][r][1];
        float mu = a * (1.f / EE);
        float var = q * (1.f / EE) - mu * mu;
        float rstd = rsqrtf(var + LN_EPS);
        float yx = (val[r].x - mu) * rstd * gx + bx;
        float yy = (val[r].y - mu) * rstd * gy + by;
        yx = yx > 0.f ? yx : (fast_exp(yx) - 1.f);
        yy = yy > 0.f ? yy : (fast_exp(yy) - 1.f);
        *(float2*)(o + ((size_t)(b * NN + i)) * EE + 2 * c) = make_float2(yx, yy);
    }
}

// ---------------------------------------------------------------------------
extern "C" void kernel_launch(void* const* d_in, const int* in_sizes, int n_in,
                              void* d_out, int out_size) {
    const float* depot_xy = (const float*)d_in[0];
    const float* node5    = (const float*)d_in[1];
    const void*  adj_raw  = (const void*)d_in[2];
    const float* depW  = (const float*)d_in[3];
    const float* depb  = (const float*)d_in[4];
    const float* nodeW = (const float*)d_in[5];
    const float* nodeb = (const float*)d_in[6];
    const float* W     = (const float*)d_in[7];
    const float* attn  = (const float*)d_in[8];
    const float* ln_g  = (const float*)d_in[9];
    const float* ln_b  = (const float*)d_in[10];
    float* out = (float*)d_out;

    probe_mask_kernel<<<1, 256>>>((const unsigned int*)adj_raw);
    convert_bits_kernel<<<BB * NN, 512>>>(adj_raw);

    embed_kernel<<<BB * NN, EE>>>(depot_xy, node5, depW, depb, nodeW, nodeb);

    dim3 agrid((NN + IT - 1) / IT, BB);
    int cur = 0;
    for (int l = 0; l < LL; l++) {
        xw_kernel<<<BB * NN / 16, 256>>>(cur,
                                         W + (size_t)l * EE * EE,
                                         attn + (size_t)l * HH * 2 * HD);
        int dst = (l == LL - 1) ? -1 : (1 - cur);
        attn_kernel<<<agrid, 256>>>(ln_g + (size_t)l * EE,
                                    ln_b + (size_t)l * EE,
                                    dst, out);
        cur = 1 - cur;
    }
}